// round 15
// baseline (speedup 1.0000x reference)
#include <cuda_runtime.h>
#include <math.h>

#define H 128
#define STEPS 64
#define F_IN 33
#define THREADS 384  // = 3*H, one thread per gate row

__global__ __launch_bounds__(THREADS, 1)
void gru_encoder_kernel(const float* __restrict__ x,        // [64,17]
                        const int*   __restrict__ ip,       // [64,8]
                        const int*   __restrict__ port,     // [64,2]
                        const float* __restrict__ hidden,   // [1,1,128]
                        const float* __restrict__ ip_emb,   // [256,1]
                        const float* __restrict__ port_emb, // [70000,4]
                        const float* __restrict__ W_ih,     // [384,33]
                        const float* __restrict__ W_hh,     // [384,128]
                        const float* __restrict__ b_ih,     // [384]
                        const float* __restrict__ b_hh,     // [384]
                        float* __restrict__ out,            // [64*128 (+128)]
                        int out_size)
{
    const int t = blockIdx.x;      // step 0..63
    const int j = threadIdx.x;     // gate row 0..383

    __shared__ float xi[F_IN + 3];   // padded
    __shared__ float h0[H];
    __shared__ float gi_s[3 * H];
    __shared__ float gh_s[3 * H];

    // ---- build xi[t] = concat(x[t] (17), ip_emb[ip[t]] (8), port_emb[port[t]] (2x4)) ----
    if (j < 17) {
        xi[j] = x[t * 17 + j];
    } else if (j < 25) {
        // ip_emb has embedding dim 1
        xi[j] = ip_emb[ip[t * 8 + (j - 17)]];
    } else if (j < 33) {
        int p = j - 25;            // 0..7
        int which = p >> 2;        // 0 or 1
        int d = p & 3;             // 0..3
        xi[j] = port_emb[port[t * 2 + which] * 4 + d];
    }
    if (j < H) h0[j] = hidden[j];
    __syncthreads();

    // ---- gi[j] = dot(xi, W_ih[j,:]) + b_ih[j] ----
    {
        float acc = b_ih[j];
        const float* wr = W_ih + j * F_IN;
        #pragma unroll
        for (int f = 0; f < F_IN; ++f)
            acc = fmaf(xi[f], __ldg(wr + f), acc);
        gi_s[j] = acc;
    }

    // ---- gh[j] = dot(h0, W_hh[j,:]) + b_hh[j]  (float4, full unroll -> high MLP) ----
    {
        float acc = b_hh[j];
        const float4* wr = reinterpret_cast<const float4*>(W_hh + j * H);
        #pragma unroll
        for (int k = 0; k < H / 4; ++k) {
            float4 w = __ldg(wr + k);
            acc = fmaf(w.x, h0[4 * k + 0], acc);
            acc = fmaf(w.y, h0[4 * k + 1], acc);
            acc = fmaf(w.z, h0[4 * k + 2], acc);
            acc = fmaf(w.w, h0[4 * k + 3], acc);
        }
        gh_s[j] = acc;
    }
    __syncthreads();

    // ---- GRU epilogue: threads 0..127 each produce one hidden element ----
    if (j < H) {
        float r = 1.0f / (1.0f + expf(-(gi_s[j]         + gh_s[j])));
        float z = 1.0f / (1.0f + expf(-(gi_s[H + j]     + gh_s[H + j])));
        float n = tanhf(gi_s[2 * H + j] + r * gh_s[2 * H + j]);
        float o = (1.0f - z) * n + z * h0[j];
        out[t * H + j] = o;
        // second tuple element: new_hidden = outputs[STEPS-1]
        if (t == STEPS - 1 && out_size >= STEPS * H + H)
            out[STEPS * H + j] = o;
    }
}

extern "C" void kernel_launch(void* const* d_in, const int* in_sizes, int n_in,
                              void* d_out, int out_size)
{
    const float* x        = (const float*)d_in[0];
    const int*   ip       = (const int*)  d_in[1];
    const int*   port     = (const int*)  d_in[2];
    const float* hidden   = (const float*)d_in[3];
    const float* ip_emb   = (const float*)d_in[4];
    const float* port_emb = (const float*)d_in[5];
    const float* W_ih     = (const float*)d_in[6];
    const float* W_hh     = (const float*)d_in[7];
    const float* b_ih     = (const float*)d_in[8];
    const float* b_hh     = (const float*)d_in[9];
    float* out = (float*)d_out;

    gru_encoder_kernel<<<STEPS, THREADS>>>(x, ip, port, hidden, ip_emb, port_emb,
                                           W_ih, W_hh, b_ih, b_hh, out, out_size);
}

// round 16
// speedup vs baseline: 1.7159x; 1.7159x over previous
#include <cuda_runtime.h>
#include <math.h>

#define H       128
#define STEPS   64
#define F_IN    33
#define SLICE   32                 // hidden columns per block
#define TSTEPS  2                  // steps per block
#define ROWS    96                 // 3 gates * SLICE
#define THREADS 256
#define NBLOCKS ((H / SLICE) * (STEPS / TSTEPS))   // 4 * 32 = 128

__global__ __launch_bounds__(THREADS, 1)
void gru_encoder_kernel(const float* __restrict__ x,        // [64,17]
                        const int*   __restrict__ ip,       // [64,8]
                        const int*   __restrict__ port,     // [64,2]
                        const float* __restrict__ hidden,   // [128]
                        const float* __restrict__ ip_emb,   // [256,1]
                        const float* __restrict__ port_emb, // [70000,4]
                        const float* __restrict__ W_ih,     // [384,33]
                        const float* __restrict__ W_hh,     // [384,128]
                        const float* __restrict__ b_ih,     // [384]
                        const float* __restrict__ b_hh,     // [384]
                        float* __restrict__ out,
                        int out_size)
{
    const int slice = blockIdx.x & 3;    // 0..3  -> hidden cols [slice*32, +32)
    const int tile  = blockIdx.x >> 2;   // 0..31 -> steps [tile*2, +2)
    const int tid   = threadIdx.x;
    const int lane  = tid & 31;
    const int wid   = tid >> 5;          // 8 warps

    __shared__ float h0_s[H];
    __shared__ float xi_s[TSTEPS][F_IN + 3];   // pad 33 -> 36
    __shared__ float wih_s[ROWS * F_IN];       // 96*33 = 3168 floats (coalesced stage)
    __shared__ float gh_s[ROWS];
    __shared__ float gi_s[TSTEPS * ROWS];

    // ---- phase 0: stage h0, xi, and the W_ih slice (all coalesced) ----
    if (tid < H) h0_s[tid] = hidden[tid];

    for (int i = tid; i < TSTEPS * F_IN; i += THREADS) {
        int s = i / F_IN, f = i - s * F_IN;
        int step = tile * TSTEPS + s;
        float v;
        if (f < 17)       v = x[step * 17 + f];
        else if (f < 25)  v = ip_emb[ip[step * 8 + (f - 17)]];        // emb dim 1
        else { int p = f - 25; v = port_emb[port[step * 2 + (p >> 2)] * 4 + (p & 3)]; }
        xi_s[s][f] = v;
    }

    {   // W_ih rows for this slice: 3 contiguous 32-row chunks, each 1056 floats,
        // 16B-aligned (1056*4 and 32*33*4 are multiples of 16) -> float4 copy.
        const int CH4 = (SLICE * F_IN) / 4;   // 264 float4 per chunk
        for (int i = tid; i < 3 * CH4; i += THREADS) {
            int g = i / CH4, o = i - g * CH4;
            const float4* src = reinterpret_cast<const float4*>(
                W_ih + (g * H + slice * SLICE) * F_IN);
            reinterpret_cast<float4*>(wih_s + g * SLICE * F_IN)[o] = src[o];
        }
    }
    __syncthreads();

    // ---- phase 1: gh[rl] = dot(W_hh[row,:], h0) + b_hh  (warp-cooperative, coalesced) ----
    {
        float4 hv = reinterpret_cast<const float4*>(h0_s)[lane];   // lane's 4 h0 elems
        float acc[12];
        #pragma unroll
        for (int k = 0; k < 12; ++k) {
            int rl  = wid * 12 + k;                                // 0..95
            int row = (rl >> 5) * H + slice * SLICE + (rl & 31);   // global gate row
            float4 w = reinterpret_cast<const float4*>(W_hh + row * H)[lane];
            acc[k] = w.x * hv.x + w.y * hv.y + w.z * hv.z + w.w * hv.w;
        }
        #pragma unroll
        for (int k = 0; k < 12; ++k) {        // 12 independent shfl chains (ILP)
            float a = acc[k];
            #pragma unroll
            for (int off = 16; off; off >>= 1)
                a += __shfl_xor_sync(0xffffffffu, a, off);
            if (lane == 0) {
                int rl  = wid * 12 + k;
                int row = (rl >> 5) * H + slice * SLICE + (rl & 31);
                gh_s[rl] = a + b_hh[row];
            }
        }
    }

    // ---- phase 2: gi[s][rl] = dot(xi[s], W_ih[row,:]) + b_ih  (from smem, conflict-free) ----
    if (tid < TSTEPS * ROWS) {                 // 192 tasks
        int s  = tid / ROWS, rl = tid - s * ROWS;
        int row = (rl >> 5) * H + slice * SLICE + (rl & 31);
        float acc = b_ih[row];
        const float* w  = wih_s + rl * F_IN;   // stride 33 == 1 mod 32 -> no conflicts
        const float* xv = xi_s[s];             // broadcast within warp
        #pragma unroll
        for (int f = 0; f < F_IN; ++f)
            acc = fmaf(w[f], xv[f], acc);
        gi_s[s * ROWS + rl] = acc;
    }
    __syncthreads();

    // ---- phase 3: GRU epilogue, 64 outputs per block ----
    if (tid < TSTEPS * SLICE) {
        int s = tid >> 5, j_in = tid & 31;
        int step = tile * TSTEPS + s;
        int jj   = slice * SLICE + j_in;
        float gi_r = gi_s[s * ROWS + j_in];
        float gi_z = gi_s[s * ROWS + 32 + j_in];
        float gi_n = gi_s[s * ROWS + 64 + j_in];
        float r = 1.0f / (1.0f + __expf(-(gi_r + gh_s[j_in])));
        float z = 1.0f / (1.0f + __expf(-(gi_z + gh_s[32 + j_in])));
        float n = tanhf(gi_n + r * gh_s[64 + j_in]);
        float o = (1.0f - z) * n + z * h0_s[jj];
        out[step * H + jj] = o;
        if (step == STEPS - 1 && out_size >= STEPS * H + H)
            out[STEPS * H + jj] = o;           // new_hidden = outputs[63]
    }
}

extern "C" void kernel_launch(void* const* d_in, const int* in_sizes, int n_in,
                              void* d_out, int out_size)
{
    const float* x        = (const float*)d_in[0];
    const int*   ip       = (const int*)  d_in[1];
    const int*   port     = (const int*)  d_in[2];
    const float* hidden   = (const float*)d_in[3];
    const float* ip_emb   = (const float*)d_in[4];
    const float* port_emb = (const float*)d_in[5];
    const float* W_ih     = (const float*)d_in[6];
    const float* W_hh     = (const float*)d_in[7];
    const float* b_ih     = (const float*)d_in[8];
    const float* b_hh     = (const float*)d_in[9];
    float* out = (float*)d_out;

    gru_encoder_kernel<<<NBLOCKS, THREADS>>>(x, ip, port, hidden, ip_emb, port_emb,
                                             W_ih, W_hh, b_ih, b_hh, out, out_size);
}

// round 17
// speedup vs baseline: 2.2356x; 1.3029x over previous
#include <cuda_runtime.h>
#include <math.h>

#define H       128
#define STEPS   64
#define F_IN    33
#define SLICE   32                 // hidden columns per block
#define TSTEPS  2                  // steps per block
#define ROWS    96                 // 3 gates * SLICE
#define THREADS 256
#define NBLOCKS ((H / SLICE) * (STEPS / TSTEPS))   // 128

__device__ __forceinline__ float fast_tanh(float v) {
    float r;
    asm("tanh.approx.f32 %0, %1;" : "=f"(r) : "f"(v));
    return r;
}

__global__ __launch_bounds__(THREADS, 1)
void gru_encoder_kernel(const float* __restrict__ x,        // [64,17]
                        const int*   __restrict__ ip,       // [64,8]
                        const int*   __restrict__ port,     // [64,2]
                        const float* __restrict__ hidden,   // [128]
                        const float* __restrict__ ip_emb,   // [256,1]
                        const float* __restrict__ port_emb, // [70000,4]
                        const float* __restrict__ W_ih,     // [384,33]
                        const float* __restrict__ W_hh,     // [384,128]
                        const float* __restrict__ b_ih,     // [384]
                        const float* __restrict__ b_hh,     // [384]
                        float* __restrict__ out,
                        int out_size)
{
    const int slice = blockIdx.x & 3;    // hidden cols [slice*32, +32)
    const int tile  = blockIdx.x >> 2;   // steps [tile*2, +2)
    const int tid   = threadIdx.x;
    const int lane  = tid & 31;
    const int wid   = tid >> 5;          // 8 warps

    __shared__ float h0_s[H];
    __shared__ float xi_s[TSTEPS][F_IN + 3];
    __shared__ float wih_s[ROWS * F_IN];       // 96*33 floats
    __shared__ float gh_s[ROWS];
    __shared__ float gi_s[TSTEPS * ROWS];

    // ---- phase 0: stage h0, xi, W_ih slice (no divisions, fully unrolled strides) ----
    if (tid < H) h0_s[tid] = hidden[tid];

    if (tid >= 128 && tid < 128 + TSTEPS * F_IN) {   // 66 one-shot gather threads
        int q = tid - 128;
        int s = (q >= F_IN) ? 1 : 0;
        int f = q - s * F_IN;
        int step = tile * TSTEPS + s;
        float v;
        if (f < 17)      v = x[step * 17 + f];
        else if (f < 25) v = ip_emb[ip[step * 8 + (f - 17)]];
        else { int p = f - 25; v = port_emb[port[step * 2 + (p >> 2)] * 4 + (p & 3)]; }
        xi_s[s][f] = v;
    }

    {   // W_ih: 3 chunks of 32 rows (1056 floats = 264 float4 each), 16B-aligned
        #pragma unroll
        for (int g = 0; g < 3; ++g) {
            const float4* src = reinterpret_cast<const float4*>(
                W_ih + (g * H + slice * SLICE) * F_IN);
            float4* dst = reinterpret_cast<float4*>(wih_s + g * SLICE * F_IN);
            dst[tid] = src[tid];                         // i = tid (0..255)
            if (tid < 8) dst[tid + 256] = src[tid + 256];
        }
    }

    // ---- phase 1: gh (runs BEFORE the barrier; h0 taken straight from global) ----
    {
        float4 hv = reinterpret_cast<const float4*>(hidden)[lane];  // coalesced 512B
        float acc[12];
        const int rbase = wid * 12;
        #pragma unroll
        for (int k = 0; k < 12; ++k) {
            int rl  = rbase + k;
            int row = (rl >> 5) * H + slice * SLICE + (rl & 31);
            float4 w = reinterpret_cast<const float4*>(W_hh + row * H)[lane];
            acc[k] = w.x * hv.x + w.y * hv.y + w.z * hv.z + w.w * hv.w;
        }
        #pragma unroll
        for (int k = 0; k < 12; ++k) {
            float a = acc[k];
            #pragma unroll
            for (int off = 16; off; off >>= 1)
                a += __shfl_xor_sync(0xffffffffu, a, off);
            acc[k] = a;
        }
        if (lane == 0) {
            #pragma unroll
            for (int k = 0; k < 12; ++k) {
                int rl  = rbase + k;
                int row = (rl >> 5) * H + slice * SLICE + (rl & 31);
                gh_s[rl] = acc[k] + b_hh[row];
            }
        }
    }
    __syncthreads();   // xi_s, wih_s, h0_s ready

    // ---- phase 2: gi from smem (stride-33 rows -> conflict-free) ----
    if (tid < TSTEPS * ROWS) {                 // 192 tasks
        int s  = (tid >= ROWS) ? 1 : 0;
        int rl = tid - s * ROWS;
        int row = (rl >> 5) * H + slice * SLICE + (rl & 31);
        float acc = b_ih[row];
        const float* w  = wih_s + rl * F_IN;
        const float* xv = xi_s[s];
        #pragma unroll
        for (int f = 0; f < F_IN; ++f)
            acc = fmaf(w[f], xv[f], acc);
        gi_s[s * ROWS + rl] = acc;
    }
    __syncthreads();

    // ---- phase 3: GRU epilogue ----
    if (tid < TSTEPS * SLICE) {                // 64 outputs
        int s = tid >> 5, j_in = tid & 31;
        int step = tile * TSTEPS + s;
        int jj   = slice * SLICE + j_in;
        float gi_r = gi_s[s * ROWS + j_in];
        float gi_z = gi_s[s * ROWS + 32 + j_in];
        float gi_n = gi_s[s * ROWS + 64 + j_in];
        float r = 1.0f / (1.0f + __expf(-(gi_r + gh_s[j_in])));
        float z = 1.0f / (1.0f + __expf(-(gi_z + gh_s[32 + j_in])));
        float n = fast_tanh(gi_n + r * gh_s[64 + j_in]);
        float o = (1.0f - z) * n + z * h0_s[jj];
        out[step * H + jj] = o;
        if (step == STEPS - 1 && out_size >= STEPS * H + H)
            out[STEPS * H + jj] = o;           // new_hidden = outputs[63]
    }
}

extern "C" void kernel_launch(void* const* d_in, const int* in_sizes, int n_in,
                              void* d_out, int out_size)
{
    const float* x        = (const float*)d_in[0];
    const int*   ip       = (const int*)  d_in[1];
    const int*   port     = (const int*)  d_in[2];
    const float* hidden   = (const float*)d_in[3];
    const float* ip_emb   = (const float*)d_in[4];
    const float* port_emb = (const float*)d_in[5];
    const float* W_ih     = (const float*)d_in[6];
    const float* W_hh     = (const float*)d_in[7];
    const float* b_ih     = (const float*)d_in[8];
    const float* b_hh     = (const float*)d_in[9];
    float* out = (float*)d_out;

    gru_encoder_kernel<<<NBLOCKS, THREADS>>>(x, ip, port, hidden, ip_emb, port_emb,
                                             W_ih, W_hh, b_ih, b_hh, out, out_size);
}